// round 13
// baseline (speedup 1.0000x reference)
#include <cuda_runtime.h>
#include <cstdint>

#define NT 400000
#define NM 40000
#define NE 400000
#define NEL 1000000
#define CH 64
#define FT 384
#define NBLK 1563   // ceil(NT/256)

// ---------------- scratch ----------------
__device__ float g_xtA[(size_t)NT * CH];
__device__ float g_xmA[(size_t)NM * CH];
__device__ float g_xtB[(size_t)NT * CH];
__device__ float g_xmB[(size_t)NM * CH];
__device__ float g_aggm[(size_t)NM * CH];
__device__ float g_zm[(size_t)NM * CH];
__device__ int   g_degt[NT];
__device__ int   g_degm[NM];
__device__ float g_invdegt[NT];
__device__ int   g_bsum[2048];
__device__ int   g_bstart[2048];
__device__ int   g_cursor[NT];
__device__ int   g_rowptr[NT];
__device__ int   g_ed2[NE];
__device__ uint32_t g_encWh[CH * FT / 2];
__device__ uint32_t g_encWl[CH * FT / 2];
__device__ uint32_t g_Wt0h[CH * CH / 2];
__device__ uint32_t g_Wt0l[CH * CH / 2];
__device__ uint32_t g_Wt1h[CH * CH / 2];
__device__ uint32_t g_Wt1l[CH * CH / 2];

// =================== mma.sync helpers ===================
__device__ __forceinline__ uint32_t smem_u32(const void* p) {
    uint32_t a;
    asm("{ .reg .u64 t; cvta.to.shared.u64 t, %1; cvt.u32.u64 %0, t; }" : "=r"(a) : "l"(p));
    return a;
}

__device__ __forceinline__ void ldsm_x4(uint32_t addr, uint32_t* r) {
    asm volatile("ldmatrix.sync.aligned.m8n8.x4.shared.b16 {%0,%1,%2,%3}, [%4];"
                 : "=r"(r[0]), "=r"(r[1]), "=r"(r[2]), "=r"(r[3]) : "r"(addr));
}

__device__ __forceinline__ void mma_bf16(float* c, const uint32_t* a, const uint32_t* b) {
    asm volatile(
        "mma.sync.aligned.m16n8k16.row.col.f32.bf16.bf16.f32 "
        "{%0,%1,%2,%3}, {%4,%5,%6,%7}, {%8,%9}, {%0,%1,%2,%3};"
        : "+f"(c[0]), "+f"(c[1]), "+f"(c[2]), "+f"(c[3])
        : "r"(a[0]), "r"(a[1]), "r"(a[2]), "r"(a[3]), "r"(b[0]), "r"(b[1]));
}

__device__ __forceinline__ void split2(float x0, float x1, uint32_t& hi, uint32_t& lo) {
    uint32_t h;
    asm("cvt.rn.bf16x2.f32 %0, %1, %2;" : "=r"(h) : "f"(x1), "f"(x0));
    float h0 = __uint_as_float(h << 16);
    float h1 = __uint_as_float(h & 0xffff0000u);
    float l0 = x0 - h0;
    float l1 = x1 - h1;
    asm("cvt.rn.bf16x2.f32 %0, %1, %2;" : "=r"(lo) : "f"(l1), "f"(l0));
    hi = h;
}

// ---------------- weight pre-split ----------------
__global__ __launch_bounds__(256) void split_w_kernel(const float* __restrict__ src,
                                                      uint32_t* __restrict__ hi,
                                                      uint32_t* __restrict__ lo, int npairs) {
    int i = blockIdx.x * 256 + threadIdx.x;
    if (i < npairs) {
        float2 v = ((const float2*)src)[i];
        uint32_t h, l;
        split2(v.x, v.y, h, l);
        hi[i] = h;
        lo[i] = l;
    }
}

#define AWS 72
#define OFF_AH 0
#define OFF_AL 18432
#define OFF_WH 36864
#define OFF_WL 46080
#define ENC_SMEM 55296

// =================== fused encoder + layer-0 thesis (complete, with CSR gather) ===================
// Stage 1: xtA = X@linW^T + linb + emb[nid]
// Stage 2: xtB = xtA@Wr_mt0^T + b_mt0 + invdeg[r]*sum_{edges of r} zm0[d]
__global__ __launch_bounds__(256, 2) void encoder_fused_kernel(
    const float* __restrict__ X, const uint32_t* __restrict__ Wh,
    const uint32_t* __restrict__ Wl,
    const float* __restrict__ bias, const int* __restrict__ nid,
    const float* __restrict__ emb,
    const uint32_t* __restrict__ W0h, const uint32_t* __restrict__ W0l,
    const float* __restrict__ bias0,
    const int* __restrict__ rowptr, const int* __restrict__ degt,
    const float* __restrict__ invt, const int* __restrict__ ed2,
    const float* __restrict__ zm,
    float* __restrict__ outA, float* __restrict__ outB) {
    extern __shared__ char sm[];
    const uint32_t sb = smem_u32(sm);
    const int tid = threadIdx.x;
    const int wid = tid >> 5;
    const int lane = tid & 31;
    const int wm = (wid & 3) * 32;
    const int wn = (wid >> 2) * 32;
    const int row0 = blockIdx.x * 128;

    const int arow = wid * 16 + (lane >> 4);
    const int acol = (lane & 15) * 4;
    const int wr = tid >> 2, seg = tid & 3;

    float acc[2][4][4];
#pragma unroll
    for (int mt = 0; mt < 2; mt++)
#pragma unroll
        for (int nt = 0; nt < 4; nt++)
#pragma unroll
            for (int j = 0; j < 4; j++) acc[mt][nt][j] = 0.f;

    const int a_row = wm + (lane & 15);
    const int a_koff = (lane >> 4) * 8;
    const int g = lane >> 3;
    const int b_row = wn + ((g >> 1) << 3) + (lane & 7);
    const int b_koff = (g & 1) << 3;

    for (int c = 0; c < 6; c++) {
        const int k0 = c * 64;
        if (c) __syncthreads();
        {
            char* dh = sm + OFF_AH;
            char* dl = sm + OFF_AL;
#pragma unroll
            for (int j = 0; j < 8; j++) {
                const int r = arow + j * 2;
                float4 v = *(const float4*)&X[(size_t)(row0 + r) * FT + k0 + acol];
                uint32_t h0, l0, h1, l1;
                split2(v.x, v.y, h0, l0);
                split2(v.z, v.w, h1, l1);
                uint32_t off = (uint32_t)(r * AWS + acol) * 2;
                *(uint2*)(dh + off) = make_uint2(h0, h1);
                *(uint2*)(dl + off) = make_uint2(l0, l1);
            }
        }
        {
            const uint32_t* sh = Wh + wr * (FT / 2) + c * 32 + seg * 8;
            const uint32_t* sl = Wl + wr * (FT / 2) + c * 32 + seg * 8;
            uint32_t* dh = (uint32_t*)(sm + OFF_WH) + wr * 36 + seg * 8;
            uint32_t* dl = (uint32_t*)(sm + OFF_WL) + wr * 36 + seg * 8;
            uint4 a0 = *(const uint4*)sh;
            uint4 a1 = *(const uint4*)(sh + 4);
            uint4 b0 = *(const uint4*)sl;
            uint4 b1 = *(const uint4*)(sl + 4);
            *(uint4*)dh = a0;
            *(uint4*)(dh + 4) = a1;
            *(uint4*)dl = b0;
            *(uint4*)(dl + 4) = b1;
        }
        __syncthreads();
#pragma unroll
        for (int ks = 0; ks < 4; ks++) {
            const int kcol = ks * 16;
            uint32_t a_h[8], a_l[8], w_h[8], w_l[8];
#pragma unroll
            for (int mt = 0; mt < 2; mt++) {
                uint32_t eoff = (uint32_t)((a_row + mt * 16) * AWS + kcol + a_koff) * 2;
                ldsm_x4(sb + OFF_AH + eoff, a_h + mt * 4);
                ldsm_x4(sb + OFF_AL + eoff, a_l + mt * 4);
            }
#pragma unroll
            for (int np = 0; np < 2; np++) {
                uint32_t eoff = (uint32_t)((b_row + np * 16) * AWS + kcol + b_koff) * 2;
                ldsm_x4(sb + OFF_WH + eoff, w_h + np * 4);
                ldsm_x4(sb + OFF_WL + eoff, w_l + np * 4);
            }
#pragma unroll
            for (int mt = 0; mt < 2; mt++)
#pragma unroll
                for (int nt = 0; nt < 4; nt++) {
                    const int bi = (nt >> 1) * 4 + (nt & 1) * 2;
                    mma_bf16(acc[mt][nt], a_h + mt * 4, w_h + bi);
                    mma_bf16(acc[mt][nt], a_h + mt * 4, w_l + bi);
                    mma_bf16(acc[mt][nt], a_l + mt * 4, w_h + bi);
                }
        }
    }

    __syncthreads();
    const int tr = lane >> 2;
    const int tc = (lane & 3) * 2;
    {
        float2 bb[4];
#pragma unroll
        for (int nt = 0; nt < 4; nt++)
            bb[nt] = *(const float2*)&bias[wn + nt * 8 + tc];
        char* dh = sm + OFF_AH;
        char* dl = sm + OFF_AL;
#pragma unroll
        for (int mt = 0; mt < 2; mt++) {
#pragma unroll
            for (int half = 0; half < 2; half++) {
                const int rl = wm + mt * 16 + tr + half * 8;
                const int r = row0 + rl;
                const int n = nid[r];
                const float* erow = &emb[(size_t)n * CH];
                float* orow = &outA[(size_t)r * CH];
#pragma unroll
                for (int nt = 0; nt < 4; nt++) {
                    const int col = wn + nt * 8 + tc;
                    float2 e = *(const float2*)&erow[col];
                    float2 o;
                    o.x = acc[mt][nt][half * 2 + 0] + bb[nt].x + e.x;
                    o.y = acc[mt][nt][half * 2 + 1] + bb[nt].y + e.y;
                    *(float2*)&orow[col] = o;
                    uint32_t h, l;
                    split2(o.x, o.y, h, l);
                    uint32_t off = (uint32_t)(rl * AWS + col) * 2;
                    *(uint32_t*)(dh + off) = h;
                    *(uint32_t*)(dl + off) = l;
                }
            }
        }
    }
    {
        const uint32_t* sh = W0h + wr * 32 + seg * 8;
        const uint32_t* sl = W0l + wr * 32 + seg * 8;
        uint32_t* dh = (uint32_t*)(sm + OFF_WH) + wr * 36 + seg * 8;
        uint32_t* dl = (uint32_t*)(sm + OFF_WL) + wr * 36 + seg * 8;
        uint4 a0 = *(const uint4*)sh;
        uint4 a1 = *(const uint4*)(sh + 4);
        uint4 b0 = *(const uint4*)sl;
        uint4 b1 = *(const uint4*)(sl + 4);
        *(uint4*)dh = a0;
        *(uint4*)(dh + 4) = a1;
        *(uint4*)dl = b0;
        *(uint4*)(dl + 4) = b1;
    }
    __syncthreads();

#pragma unroll
    for (int mt = 0; mt < 2; mt++)
#pragma unroll
        for (int nt = 0; nt < 4; nt++)
#pragma unroll
            for (int j = 0; j < 4; j++) acc[mt][nt][j] = 0.f;

#pragma unroll
    for (int ks = 0; ks < 4; ks++) {
        const int kcol = ks * 16;
        uint32_t a_h[8], a_l[8], w_h[8], w_l[8];
#pragma unroll
        for (int mt = 0; mt < 2; mt++) {
            uint32_t eoff = (uint32_t)((a_row + mt * 16) * AWS + kcol + a_koff) * 2;
            ldsm_x4(sb + OFF_AH + eoff, a_h + mt * 4);
            ldsm_x4(sb + OFF_AL + eoff, a_l + mt * 4);
        }
#pragma unroll
        for (int np = 0; np < 2; np++) {
            uint32_t eoff = (uint32_t)((b_row + np * 16) * AWS + kcol + b_koff) * 2;
            ldsm_x4(sb + OFF_WH + eoff, w_h + np * 4);
            ldsm_x4(sb + OFF_WL + eoff, w_l + np * 4);
        }
#pragma unroll
        for (int mt = 0; mt < 2; mt++)
#pragma unroll
            for (int nt = 0; nt < 4; nt++) {
                const int bi = (nt >> 1) * 4 + (nt & 1) * 2;
                mma_bf16(acc[mt][nt], a_h + mt * 4, w_h + bi);
                mma_bf16(acc[mt][nt], a_h + mt * 4, w_l + bi);
                mma_bf16(acc[mt][nt], a_l + mt * 4, w_h + bi);
            }
    }

    {
        float2 bb[4];
#pragma unroll
        for (int nt = 0; nt < 4; nt++)
            bb[nt] = *(const float2*)&bias0[wn + nt * 8 + tc];
#pragma unroll
        for (int mt = 0; mt < 2; mt++) {
#pragma unroll
            for (int half = 0; half < 2; half++) {
                const int r = row0 + wm + mt * 16 + tr + half * 8;
                float* orow = &outB[(size_t)r * CH];
                const int rp = rowptr[r];
                const int dg = degt[r];
                const float inv = invt[r];
                float2 ag[4];
#pragma unroll
                for (int nt = 0; nt < 4; nt++) ag[nt] = make_float2(0.f, 0.f);
                for (int j = 0; j < dg; j++) {
                    const int d = __ldg(&ed2[rp + j]);
                    const float* zrow = &zm[(size_t)d * CH];
#pragma unroll
                    for (int nt = 0; nt < 4; nt++) {
                        float2 z = *(const float2*)&zrow[wn + nt * 8 + tc];
                        ag[nt].x += z.x;
                        ag[nt].y += z.y;
                    }
                }
#pragma unroll
                for (int nt = 0; nt < 4; nt++) {
                    const int col = wn + nt * 8 + tc;
                    float2 o;
                    o.x = acc[mt][nt][half * 2 + 0] + bb[nt].x + ag[nt].x * inv;
                    o.y = acc[mt][nt][half * 2 + 1] + bb[nt].y + ag[nt].y * inv;
                    *(float2*)&orow[col] = o;
                }
            }
        }
    }
}

// =================== thesis combined (layer 1): out = relu(x)@Wr^T + b + agg ===================
__global__ __launch_bounds__(256, 2) void thesis_comb_kernel(
    const float* __restrict__ Xin,
    const uint32_t* __restrict__ Wh, const uint32_t* __restrict__ Wl,
    const float* __restrict__ bias,
    const int* __restrict__ rowptr, const int* __restrict__ degt,
    const float* __restrict__ invt, const int* __restrict__ ed2,
    const float* __restrict__ zm,
    float* __restrict__ out) {
    extern __shared__ char sm[];
    const uint32_t sb = smem_u32(sm);
    const int tid = threadIdx.x;
    const int wid = tid >> 5;
    const int lane = tid & 31;
    const int wm = (wid & 3) * 32;
    const int wn = (wid >> 2) * 32;
    const int row0 = blockIdx.x * 128;

    const int arow = wid * 16 + (lane >> 4);
    const int acol = (lane & 15) * 4;
    const int wr = tid >> 2, seg = tid & 3;

    {
        char* dh = sm + OFF_AH;
        char* dl = sm + OFF_AL;
#pragma unroll
        for (int j = 0; j < 8; j++) {
            const int r = arow + j * 2;
            float4 v = *(const float4*)&Xin[(size_t)(row0 + r) * CH + acol];
            v.x = fmaxf(v.x, 0.f); v.y = fmaxf(v.y, 0.f);
            v.z = fmaxf(v.z, 0.f); v.w = fmaxf(v.w, 0.f);
            uint32_t h0, l0, h1, l1;
            split2(v.x, v.y, h0, l0);
            split2(v.z, v.w, h1, l1);
            uint32_t off = (uint32_t)(r * AWS + acol) * 2;
            *(uint2*)(dh + off) = make_uint2(h0, h1);
            *(uint2*)(dl + off) = make_uint2(l0, l1);
        }
    }
    {
        const uint32_t* sh = Wh + wr * 32 + seg * 8;
        const uint32_t* sl = Wl + wr * 32 + seg * 8;
        uint32_t* dh = (uint32_t*)(sm + OFF_WH) + wr * 36 + seg * 8;
        uint32_t* dl = (uint32_t*)(sm + OFF_WL) + wr * 36 + seg * 8;
        uint4 a0 = *(const uint4*)sh;
        uint4 a1 = *(const uint4*)(sh + 4);
        uint4 b0 = *(const uint4*)sl;
        uint4 b1 = *(const uint4*)(sl + 4);
        *(uint4*)dh = a0;
        *(uint4*)(dh + 4) = a1;
        *(uint4*)dl = b0;
        *(uint4*)(dl + 4) = b1;
    }
    __syncthreads();

    float acc[2][4][4];
#pragma unroll
    for (int mt = 0; mt < 2; mt++)
#pragma unroll
        for (int nt = 0; nt < 4; nt++)
#pragma unroll
            for (int j = 0; j < 4; j++) acc[mt][nt][j] = 0.f;

    const int a_row = wm + (lane & 15);
    const int a_koff = (lane >> 4) * 8;
    const int g = lane >> 3;
    const int b_row = wn + ((g >> 1) << 3) + (lane & 7);
    const int b_koff = (g & 1) << 3;

#pragma unroll
    for (int ks = 0; ks < 4; ks++) {
        const int kcol = ks * 16;
        uint32_t a_h[8], a_l[8], w_h[8], w_l[8];
#pragma unroll
        for (int mt = 0; mt < 2; mt++) {
            uint32_t eoff = (uint32_t)((a_row + mt * 16) * AWS + kcol + a_koff) * 2;
            ldsm_x4(sb + OFF_AH + eoff, a_h + mt * 4);
            ldsm_x4(sb + OFF_AL + eoff, a_l + mt * 4);
        }
#pragma unroll
        for (int np = 0; np < 2; np++) {
            uint32_t eoff = (uint32_t)((b_row + np * 16) * AWS + kcol + b_koff) * 2;
            ldsm_x4(sb + OFF_WH + eoff, w_h + np * 4);
            ldsm_x4(sb + OFF_WL + eoff, w_l + np * 4);
        }
#pragma unroll
        for (int mt = 0; mt < 2; mt++)
#pragma unroll
            for (int nt = 0; nt < 4; nt++) {
                const int bi = (nt >> 1) * 4 + (nt & 1) * 2;
                mma_bf16(acc[mt][nt], a_h + mt * 4, w_h + bi);
                mma_bf16(acc[mt][nt], a_h + mt * 4, w_l + bi);
                mma_bf16(acc[mt][nt], a_l + mt * 4, w_h + bi);
            }
    }

    const int tr = lane >> 2;
    const int tc = (lane & 3) * 2;
    float2 bb[4];
#pragma unroll
    for (int nt = 0; nt < 4; nt++)
        bb[nt] = *(const float2*)&bias[wn + nt * 8 + tc];
#pragma unroll
    for (int mt = 0; mt < 2; mt++) {
#pragma unroll
        for (int half = 0; half < 2; half++) {
            const int r = row0 + wm + mt * 16 + tr + half * 8;
            float* orow = &out[(size_t)r * CH];
            const int rp = rowptr[r];
            const int dg = degt[r];
            const float inv = invt[r];
            float2 ag[4];
#pragma unroll
            for (int nt = 0; nt < 4; nt++) ag[nt] = make_float2(0.f, 0.f);
            for (int j = 0; j < dg; j++) {
                const int d = __ldg(&ed2[rp + j]);
                const float* zrow = &zm[(size_t)d * CH];
#pragma unroll
                for (int nt = 0; nt < 4; nt++) {
                    float2 z = *(const float2*)&zrow[wn + nt * 8 + tc];
                    ag[nt].x += z.x;
                    ag[nt].y += z.y;
                }
            }
#pragma unroll
            for (int nt = 0; nt < 4; nt++) {
                const int col = wn + nt * 8 + tc;
                float2 o;
                o.x = acc[mt][nt][half * 2 + 0] + bb[nt].x + ag[nt].x * inv;
                o.y = acc[mt][nt][half * 2 + 1] + bb[nt].y + ag[nt].y * inv;
                *(float2*)&orow[col] = o;
            }
        }
    }
}

// ---------------- small kernels ----------------
__global__ __launch_bounds__(256) void zero_deg_kernel(int* degt, int* degm) {
    int i = blockIdx.x * 256 + threadIdx.x;
    if (i < NT) degt[i] = 0;
    if (i < NM) degm[i] = 0;
}

__global__ __launch_bounds__(256) void degree_kernel(const int* __restrict__ esrc,
                                                     const int* __restrict__ edst,
                                                     int* degt, int* degm) {
    int e = blockIdx.x * 256 + threadIdx.x;
    if (e < NE) {
        atomicAdd(&degm[edst[e]], 1);
        atomicAdd(&degt[esrc[e]], 1);
    }
}

// ---- counting-sort of edge dst by source (CSR build) ----
__global__ __launch_bounds__(256) void blocksum_kernel(const int* __restrict__ degt,
                                                       int* __restrict__ bsum) {
    __shared__ int s[256];
    int i = blockIdx.x * 256 + threadIdx.x;
    s[threadIdx.x] = (i < NT) ? degt[i] : 0;
    __syncthreads();
#pragma unroll
    for (int o = 128; o > 0; o >>= 1) {
        if (threadIdx.x < o) s[threadIdx.x] += s[threadIdx.x + o];
        __syncthreads();
    }
    if (threadIdx.x == 0) bsum[blockIdx.x] = s[0];
}

__global__ __launch_bounds__(1024) void scan_kernel(const int* __restrict__ bsum,
                                                    int* __restrict__ bstart) {
    __shared__ int p[1024];
    int t = threadIdx.x;
    int a = (2 * t < NBLK) ? bsum[2 * t] : 0;
    int b = (2 * t + 1 < NBLK) ? bsum[2 * t + 1] : 0;
    p[t] = a + b;
    __syncthreads();
    for (int o = 1; o < 1024; o <<= 1) {
        int v = (t >= o) ? p[t - o] : 0;
        __syncthreads();
        p[t] += v;
        __syncthreads();
    }
    int incl1 = p[t];
    int incl0 = incl1 - b;
    if (2 * t < NBLK) bstart[2 * t] = incl0 - a;
    if (2 * t + 1 < NBLK) bstart[2 * t + 1] = incl1 - b;
}

__global__ __launch_bounds__(256) void offsets_kernel(const int* __restrict__ degt,
                                                      const int* __restrict__ bstart,
                                                      int* __restrict__ cursor,
                                                      int* __restrict__ rowptr,
                                                      float* __restrict__ invt) {
    __shared__ int s[256];
    int t = threadIdx.x;
    int i = blockIdx.x * 256 + t;
    int d = (i < NT) ? degt[i] : 0;
    s[t] = d;
    __syncthreads();
    for (int o = 1; o < 256; o <<= 1) {
        int v = (t >= o) ? s[t - o] : 0;
        __syncthreads();
        s[t] += v;
        __syncthreads();
    }
    if (i < NT) {
        int start = bstart[blockIdx.x] + s[t] - d;
        cursor[i] = start;
        rowptr[i] = start;
        invt[i] = 1.0f / (float)(d > 0 ? d : 1);
    }
}

__global__ __launch_bounds__(256) void edge_sort_kernel(const int* __restrict__ esrc,
                                                        const int* __restrict__ edst,
                                                        int* cursor,
                                                        int* __restrict__ ed2) {
    int e = blockIdx.x * 256 + threadIdx.x;
    if (e < NE) {
        int s = esrc[e];
        int pos = atomicAdd(&cursor[s], 1);
        ed2[pos] = edst[e];
    }
}

__global__ __launch_bounds__(256) void copy_xm_kernel(const float* __restrict__ embm,
                                                      const int* __restrict__ mid,
                                                      float* __restrict__ xm) {
    int idx = blockIdx.x * 256 + threadIdx.x;
    int i = idx >> 4;
    int q = (idx & 15) << 2;
    int n = mid[i];
    *(float4*)&xm[(size_t)i * CH + q] = *(const float4*)&embm[(size_t)n * CH + q];
}

// ---------------- z_m = x_m @ Wl_mt^T  (+ zero aggm slice) ----------------
__global__ __launch_bounds__(256) void zm_kernel(const float* __restrict__ Xin,
                                                 const float* __restrict__ W,
                                                 float* __restrict__ out,
                                                 float* __restrict__ aggm) {
    __shared__ float Xs[64 * 68];
    __shared__ float Ws[64 * 68];
    int tid = threadIdx.x;
    int tx = tid & 15, ty = tid >> 4;
    int row0 = blockIdx.x * 64;
    {
        float4* dst = (float4*)&aggm[(size_t)row0 * CH];
        float4 z = make_float4(0.f, 0.f, 0.f, 0.f);
#pragma unroll
        for (int i = 0; i < 4; i++) dst[i * 256 + tid] = z;
    }
#pragma unroll
    for (int it = 0; it < 4; it++) {
        int f = it * 256 + tid;
        int r = f >> 4;
        int kq = (f & 15) << 2;
        *(float4*)&Xs[r * 68 + kq] = *(const float4*)&Xin[(size_t)(row0 + r) * CH + kq];
        float4 v = *(const float4*)&W[r * CH + kq];
        Ws[(kq + 0) * 68 + r] = v.x;
        Ws[(kq + 1) * 68 + r] = v.y;
        Ws[(kq + 2) * 68 + r] = v.z;
        Ws[(kq + 3) * 68 + r] = v.w;
    }
    __syncthreads();
    float acc[4][4] = {};
#pragma unroll 8
    for (int k = 0; k < 64; k++) {
        float4 b4 = *(const float4*)&Ws[k * 68 + tx * 4];
#pragma unroll
        for (int i = 0; i < 4; i++) {
            float a = Xs[(ty * 4 + i) * 68 + k];
            acc[i][0] += a * b4.x;
            acc[i][1] += a * b4.y;
            acc[i][2] += a * b4.z;
            acc[i][3] += a * b4.w;
        }
    }
#pragma unroll
    for (int i = 0; i < 4; i++) {
        int r = row0 + ty * 4 + i;
        float4 o = make_float4(acc[i][0], acc[i][1], acc[i][2], acc[i][3]);
        *(float4*)&out[(size_t)r * CH + tx * 4] = o;
    }
}

// ---------------- aggm-only edge scatter ----------------
__global__ __launch_bounds__(256) void scatter_aggm_kernel(
    const float* __restrict__ xt,
    const int* __restrict__ esrc, const int* __restrict__ edst,
    float* aggm, int relu_in) {
    int idx = blockIdx.x * 256 + threadIdx.x;
    int e = idx >> 4;
    int q = (idx & 15) << 2;
    int s = __ldg(&esrc[e]);
    int d = __ldg(&edst[e]);
    float4 v = *(const float4*)&xt[(size_t)s * CH + q];
    if (relu_in) {
        v.x = fmaxf(v.x, 0.f); v.y = fmaxf(v.y, 0.f);
        v.z = fmaxf(v.z, 0.f); v.w = fmaxf(v.w, 0.f);
    }
    float* pm = &aggm[(size_t)d * CH + q];
    asm volatile("red.global.add.v4.f32 [%0], {%1,%2,%3,%4};"
                 :: "l"(pm), "f"(v.x), "f"(v.y), "f"(v.z), "f"(v.w) : "memory");
}

// ---------------- mentor update ----------------
__global__ __launch_bounds__(256) void mentor_kernel(const float* __restrict__ xm,
                                                     const float* __restrict__ aggm,
                                                     const int* __restrict__ degm,
                                                     const float* __restrict__ Wl,
                                                     const float* __restrict__ Wr,
                                                     const float* __restrict__ bias,
                                                     float* __restrict__ out, int relu) {
    __shared__ float Xs[64 * 68];
    __shared__ float Ws[64 * 68];
    int tid = threadIdx.x;
    int tx = tid & 15, ty = tid >> 4;
    int row0 = blockIdx.x * 64;
    float acc[4][4] = {};

    for (int p = 0; p < 2; p++) {
        __syncthreads();
        const float* A = p ? xm : aggm;
        const float* W = p ? Wr : Wl;
#pragma unroll
        for (int it = 0; it < 4; it++) {
            int f = it * 256 + tid;
            int r = f >> 4;
            int kq = (f & 15) << 2;
            float4 v = *(const float4*)&A[(size_t)(row0 + r) * CH + kq];
            if (p == 0) {
                int dg = degm[row0 + r];
                float inv = 1.0f / (float)(dg > 0 ? dg : 1);
                v.x *= inv; v.y *= inv; v.z *= inv; v.w *= inv;
            }
            *(float4*)&Xs[r * 68 + kq] = v;
            float4 wv = *(const float4*)&W[r * CH + kq];
            Ws[(kq + 0) * 68 + r] = wv.x;
            Ws[(kq + 1) * 68 + r] = wv.y;
            Ws[(kq + 2) * 68 + r] = wv.z;
            Ws[(kq + 3) * 68 + r] = wv.w;
        }
        __syncthreads();
#pragma unroll 8
        for (int k = 0; k < 64; k++) {
            float4 b4 = *(const float4*)&Ws[k * 68 + tx * 4];
#pragma unroll
            for (int i = 0; i < 4; i++) {
                float a = Xs[(ty * 4 + i) * 68 + k];
                acc[i][0] += a * b4.x;
                acc[i][1] += a * b4.y;
                acc[i][2] += a * b4.z;
                acc[i][3] += a * b4.w;
            }
        }
    }
    float4 bb = *(const float4*)&bias[tx * 4];
#pragma unroll
    for (int i = 0; i < 4; i++) {
        int r = row0 + ty * 4 + i;
        float4 o;
        o.x = acc[i][0] + bb.x;
        o.y = acc[i][1] + bb.y;
        o.z = acc[i][2] + bb.z;
        o.w = acc[i][3] + bb.w;
        if (relu) {
            o.x = fmaxf(o.x, 0.f); o.y = fmaxf(o.y, 0.f);
            o.z = fmaxf(o.z, 0.f); o.w = fmaxf(o.w, 0.f);
        }
        *(float4*)&out[(size_t)r * CH + tx * 4] = o;
    }
}

// ---------------- edge dot classifier ----------------
__global__ __launch_bounds__(256) void dot_kernel(const float* __restrict__ xt,
                                                  const float* __restrict__ xm,
                                                  const int* __restrict__ els,
                                                  const int* __restrict__ eld,
                                                  float* __restrict__ out) {
    int idx = blockIdx.x * 256 + threadIdx.x;
    int e = idx >> 4;
    int q = (idx & 15) << 2;
    int s = __ldg(&els[e]);
    int d = __ldg(&eld[e]);
    float4 a = *(const float4*)&xt[(size_t)s * CH + q];
    float4 b = *(const float4*)&xm[(size_t)d * CH + q];
    float p = a.x * b.x + a.y * b.y + a.z * b.z + a.w * b.w;
    p += __shfl_xor_sync(0xffffffffu, p, 8);
    p += __shfl_xor_sync(0xffffffffu, p, 4);
    p += __shfl_xor_sync(0xffffffffu, p, 2);
    p += __shfl_xor_sync(0xffffffffu, p, 1);
    if ((idx & 15) == 0) out[e] = p;
}

// ---------------- launcher ----------------
extern "C" void kernel_launch(void* const* d_in, const int* in_sizes, int n_in,
                              void* d_out, int out_size) {
    const float* x_thesis = (const float*)d_in[0];
    const int*   tnid     = (const int*)d_in[1];
    const int*   mnid     = (const int*)d_in[2];
    const int*   esrc     = (const int*)d_in[3];
    const int*   edst     = (const int*)d_in[4];
    const int*   els      = (const int*)d_in[5];
    const int*   eld      = (const int*)d_in[6];
    const float* linW     = (const float*)d_in[7];
    const float* linb     = (const float*)d_in[8];
    const float* embt     = (const float*)d_in[9];
    const float* embm     = (const float*)d_in[10];
    float* out = (float*)d_out;

    float *p_xtA, *p_xtB, *p_xmA, *p_xmB, *p_aggm, *p_zm, *p_invt;
    int *p_degt, *p_degm, *p_bsum, *p_bstart, *p_cursor, *p_rowptr, *p_ed2;
    uint32_t *p_eWh, *p_eWl, *p_W0h, *p_W0l, *p_W1h, *p_W1l;
    cudaGetSymbolAddress((void**)&p_xtA, g_xtA);
    cudaGetSymbolAddress((void**)&p_xtB, g_xtB);
    cudaGetSymbolAddress((void**)&p_xmA, g_xmA);
    cudaGetSymbolAddress((void**)&p_xmB, g_xmB);
    cudaGetSymbolAddress((void**)&p_aggm, g_aggm);
    cudaGetSymbolAddress((void**)&p_zm, g_zm);
    cudaGetSymbolAddress((void**)&p_degt, g_degt);
    cudaGetSymbolAddress((void**)&p_degm, g_degm);
    cudaGetSymbolAddress((void**)&p_invt, g_invdegt);
    cudaGetSymbolAddress((void**)&p_bsum, g_bsum);
    cudaGetSymbolAddress((void**)&p_bstart, g_bstart);
    cudaGetSymbolAddress((void**)&p_cursor, g_cursor);
    cudaGetSymbolAddress((void**)&p_rowptr, g_rowptr);
    cudaGetSymbolAddress((void**)&p_ed2, g_ed2);
    cudaGetSymbolAddress((void**)&p_eWh, g_encWh);
    cudaGetSymbolAddress((void**)&p_eWl, g_encWl);
    cudaGetSymbolAddress((void**)&p_W0h, g_Wt0h);
    cudaGetSymbolAddress((void**)&p_W0l, g_Wt0l);
    cudaGetSymbolAddress((void**)&p_W1h, g_Wt1h);
    cudaGetSymbolAddress((void**)&p_W1l, g_Wt1l);

    cudaFuncSetAttribute(encoder_fused_kernel,
                         cudaFuncAttributeMaxDynamicSharedMemorySize, ENC_SMEM);
    cudaFuncSetAttribute(thesis_comb_kernel,
                         cudaFuncAttributeMaxDynamicSharedMemorySize, ENC_SMEM);

    // weight pre-splits
    split_w_kernel<<<(CH * FT / 2 + 255) / 256, 256>>>(linW, p_eWh, p_eWl, CH * FT / 2);
    split_w_kernel<<<(CH * CH / 2 + 255) / 256, 256>>>((const float*)d_in[15], p_W0h, p_W0l, CH * CH / 2);
    split_w_kernel<<<(CH * CH / 2 + 255) / 256, 256>>>((const float*)d_in[21], p_W1h, p_W1l, CH * CH / 2);
    // graph prep + CSR build
    zero_deg_kernel<<<(NT + 255) / 256, 256>>>(p_degt, p_degm);
    degree_kernel<<<(NE + 255) / 256, 256>>>(esrc, edst, p_degt, p_degm);
    blocksum_kernel<<<NBLK, 256>>>(p_degt, p_bsum);
    scan_kernel<<<1, 1024>>>(p_bsum, p_bstart);
    offsets_kernel<<<NBLK, 256>>>(p_degt, p_bstart, p_cursor, p_rowptr, p_invt);
    edge_sort_kernel<<<(NE + 255) / 256, 256>>>(esrc, edst, p_cursor, p_ed2);
    // mentor features + zm0 before encoder
    copy_xm_kernel<<<NM * 16 / 256, 256>>>(embm, mnid, p_xmA);
    zm_kernel<<<NM / 64, 256>>>(p_xmA, (const float*)d_in[14], p_zm, p_aggm);
    // fused encoder + complete layer-0 thesis (with CSR agg gather)
    encoder_fused_kernel<<<NT / 128, 256, ENC_SMEM>>>(x_thesis, p_eWh, p_eWl, linb, tnid, embt,
                                                      p_W0h, p_W0l, (const float*)d_in[16],
                                                      p_rowptr, p_degt, p_invt, p_ed2, p_zm,
                                                      p_xtA, p_xtB);

    // ---- layer 0 mentor side ----
    scatter_aggm_kernel<<<NE * 16 / 256, 256>>>(p_xtA, esrc, edst, p_aggm, 0);
    mentor_kernel<<<NM / 64, 256>>>(p_xmA, p_aggm, p_degm,
                                    (const float*)d_in[11], (const float*)d_in[12],
                                    (const float*)d_in[13], p_xmB, 1);

    // ---- layer 1 ----
    zm_kernel<<<NM / 64, 256>>>(p_xmB, (const float*)d_in[20], p_zm, p_aggm);
    thesis_comb_kernel<<<NT / 128, 256, ENC_SMEM>>>(p_xtB, p_W1h, p_W1l,
                                                    (const float*)d_in[22],
                                                    p_rowptr, p_degt, p_invt, p_ed2, p_zm,
                                                    p_xtA);
    scatter_aggm_kernel<<<NE * 16 / 256, 256>>>(p_xtB, esrc, edst, p_aggm, 1);
    mentor_kernel<<<NM / 64, 256>>>(p_xmB, p_aggm, p_degm,
                                    (const float*)d_in[17], (const float*)d_in[18],
                                    (const float*)d_in[19], p_xmA, 0);

    dot_kernel<<<NEL * 16 / 256, 256>>>(p_xtA, p_xmA, els, eld, out);
}

// round 15
// speedup vs baseline: 1.2230x; 1.2230x over previous
#include <cuda_runtime.h>
#include <cstdint>

#define NT 400000
#define NM 40000
#define NE 400000
#define NEL 1000000
#define CH 64
#define FT 384

// ---------------- scratch ----------------
__device__ float g_xtA[(size_t)NT * CH];
__device__ float g_xmA[(size_t)NM * CH];
__device__ float g_xtB[(size_t)NT * CH];
__device__ float g_xmB[(size_t)NM * CH];
__device__ float g_aggm[(size_t)NM * CH];
__device__ float g_zm[(size_t)NM * CH];
__device__ int   g_degt[NT];
__device__ int   g_degm[NM];
__device__ float g_invdegt[NT];
__device__ uint32_t g_encWh[CH * FT / 2];
__device__ uint32_t g_encWl[CH * FT / 2];
__device__ uint32_t g_Wt0h[CH * CH / 2];
__device__ uint32_t g_Wt0l[CH * CH / 2];
__device__ uint32_t g_Wt1h[CH * CH / 2];
__device__ uint32_t g_Wt1l[CH * CH / 2];

// =================== mma.sync helpers ===================
__device__ __forceinline__ uint32_t smem_u32(const void* p) {
    uint32_t a;
    asm("{ .reg .u64 t; cvta.to.shared.u64 t, %1; cvt.u32.u64 %0, t; }" : "=r"(a) : "l"(p));
    return a;
}

__device__ __forceinline__ void ldsm_x4(uint32_t addr, uint32_t* r) {
    asm volatile("ldmatrix.sync.aligned.m8n8.x4.shared.b16 {%0,%1,%2,%3}, [%4];"
                 : "=r"(r[0]), "=r"(r[1]), "=r"(r[2]), "=r"(r[3]) : "r"(addr));
}

__device__ __forceinline__ void mma_bf16(float* c, const uint32_t* a, const uint32_t* b) {
    asm volatile(
        "mma.sync.aligned.m16n8k16.row.col.f32.bf16.bf16.f32 "
        "{%0,%1,%2,%3}, {%4,%5,%6,%7}, {%8,%9}, {%0,%1,%2,%3};"
        : "+f"(c[0]), "+f"(c[1]), "+f"(c[2]), "+f"(c[3])
        : "r"(a[0]), "r"(a[1]), "r"(a[2]), "r"(a[3]), "r"(b[0]), "r"(b[1]));
}

__device__ __forceinline__ void split2(float x0, float x1, uint32_t& hi, uint32_t& lo) {
    uint32_t h;
    asm("cvt.rn.bf16x2.f32 %0, %1, %2;" : "=r"(h) : "f"(x1), "f"(x0));
    float h0 = __uint_as_float(h << 16);
    float h1 = __uint_as_float(h & 0xffff0000u);
    float l0 = x0 - h0;
    float l1 = x1 - h1;
    asm("cvt.rn.bf16x2.f32 %0, %1, %2;" : "=r"(lo) : "f"(l1), "f"(l0));
    hi = h;
}

// ---------------- weight pre-split ----------------
__global__ __launch_bounds__(256) void split_w_kernel(const float* __restrict__ src,
                                                      uint32_t* __restrict__ hi,
                                                      uint32_t* __restrict__ lo, int npairs) {
    int i = blockIdx.x * 256 + threadIdx.x;
    if (i < npairs) {
        float2 v = ((const float2*)src)[i];
        uint32_t h, l;
        split2(v.x, v.y, h, l);
        hi[i] = h;
        lo[i] = l;
    }
}

#define AWS 72
#define OFF_AH 0
#define OFF_AL 18432
#define OFF_WH 36864
#define OFF_WL 46080
#define OFF_RAW 55296          // 32 KB fp32 staging for cp.async pipeline
#define ENC_SMEM (55296 + 32768)
#define TB_SMEM 55296

// =================== fused encoder + layer-0 thesis base (cp.async pipelined) ===================
// Stage 1: xtA = X@linW^T + linb + emb[nid]   (K=384, 6 chunks; raw A prefetched async)
// Stage 2: xtB = xtA@Wr_mt0^T + b_mt0        (K=64, tile reused from smem)
__global__ __launch_bounds__(256, 2) void encoder_fused_kernel(
    const float* __restrict__ X, const uint32_t* __restrict__ Wh,
    const uint32_t* __restrict__ Wl,
    const float* __restrict__ bias, const int* __restrict__ nid,
    const float* __restrict__ emb,
    const uint32_t* __restrict__ W0h, const uint32_t* __restrict__ W0l,
    const float* __restrict__ bias0,
    float* __restrict__ outA, float* __restrict__ outB) {
    extern __shared__ char sm[];
    const uint32_t sb = smem_u32(sm);
    const int tid = threadIdx.x;
    const int wid = tid >> 5;
    const int lane = tid & 31;
    const int wm = (wid & 3) * 32;
    const int wn = (wid >> 2) * 32;
    const int row0 = blockIdx.x * 128;

    // coalesced A-producer mapping: each half-warp covers one row's 256B segment
    const int arow = wid * 16 + (lane >> 4);   // row base (stride 2 over j)
    const int acol = (lane & 15) * 4;          // float4 col within 64-col chunk
    const int wr = tid >> 2, seg = tid & 3;    // W producer

    float acc[2][4][4];
#pragma unroll
    for (int mt = 0; mt < 2; mt++)
#pragma unroll
        for (int nt = 0; nt < 4; nt++)
#pragma unroll
            for (int j = 0; j < 4; j++) acc[mt][nt][j] = 0.f;

    const int a_row = wm + (lane & 15);
    const int a_koff = (lane >> 4) * 8;
    const int g = lane >> 3;
    const int b_row = wn + ((g >> 1) << 3) + (lane & 7);
    const int b_koff = (g & 1) << 3;

    // staging addresses (per-thread, fixed per chunk-relative layout)
    const uint32_t stg = sb + OFF_RAW + (uint32_t)(arow * 64 + acol) * 4;

    // prefetch chunk 0
    {
        const float* src = &X[(size_t)(row0 + arow) * FT + acol];
#pragma unroll
        for (int j = 0; j < 8; j++)
            asm volatile("cp.async.cg.shared.global [%0], [%1], 16;"
                         :: "r"(stg + (uint32_t)(j * 2 * 64 * 4)),
                            "l"(src + (size_t)j * 2 * FT) : "memory");
        asm volatile("cp.async.commit_group;" ::: "memory");
    }

    // ---- stage 1: K=384 ----
    for (int c = 0; c < 6; c++) {
        asm volatile("cp.async.wait_group 0;" ::: "memory");
        __syncthreads();   // staging(c) visible; bf16 bufs free (previous consume done)
        // produce: split raw chunk from smem staging -> bf16 hi/lo
        {
            char* dh = sm + OFF_AH;
            char* dl = sm + OFF_AL;
#pragma unroll
            for (int j = 0; j < 8; j++) {
                const int r = arow + j * 2;
                float4 v = *(const float4*)(sm + OFF_RAW + (uint32_t)(r * 64 + acol) * 4);
                uint32_t h0, l0, h1, l1;
                split2(v.x, v.y, h0, l0);
                split2(v.z, v.w, h1, l1);
                uint32_t off = (uint32_t)(r * AWS + acol) * 2;
                *(uint2*)(dh + off) = make_uint2(h0, h1);
                *(uint2*)(dl + off) = make_uint2(l0, l1);
            }
        }
        // load pre-split W chunk: 64 rows x 32 u32
        {
            const uint32_t* sh = Wh + wr * (FT / 2) + c * 32 + seg * 8;
            const uint32_t* sl = Wl + wr * (FT / 2) + c * 32 + seg * 8;
            uint32_t* dh = (uint32_t*)(sm + OFF_WH) + wr * 36 + seg * 8;
            uint32_t* dl = (uint32_t*)(sm + OFF_WL) + wr * 36 + seg * 8;
            uint4 a0 = *(const uint4*)sh;
            uint4 a1 = *(const uint4*)(sh + 4);
            uint4 b0 = *(const uint4*)sl;
            uint4 b1 = *(const uint4*)(sl + 4);
            *(uint4*)dh = a0;
            *(uint4*)(dh + 4) = a1;
            *(uint4*)dl = b0;
            *(uint4*)(dl + 4) = b1;
        }
        __syncthreads();   // bf16 ready; staging fully consumed by producers
        // prefetch next chunk (overlaps with mma phase)
        if (c < 5) {
            const float* src = &X[(size_t)(row0 + arow) * FT + (c + 1) * 64 + acol];
#pragma unroll
            for (int j = 0; j < 8; j++)
                asm volatile("cp.async.cg.shared.global [%0], [%1], 16;"
                             :: "r"(stg + (uint32_t)(j * 2 * 64 * 4)),
                                "l"(src + (size_t)j * 2 * FT) : "memory");
            asm volatile("cp.async.commit_group;" ::: "memory");
        }
        // consume: 4 k16 steps x 3 products
#pragma unroll
        for (int ks = 0; ks < 4; ks++) {
            const int kcol = ks * 16;
            uint32_t a_h[8], a_l[8], w_h[8], w_l[8];
#pragma unroll
            for (int mt = 0; mt < 2; mt++) {
                uint32_t eoff = (uint32_t)((a_row + mt * 16) * AWS + kcol + a_koff) * 2;
                ldsm_x4(sb + OFF_AH + eoff, a_h + mt * 4);
                ldsm_x4(sb + OFF_AL + eoff, a_l + mt * 4);
            }
#pragma unroll
            for (int np = 0; np < 2; np++) {
                uint32_t eoff = (uint32_t)((b_row + np * 16) * AWS + kcol + b_koff) * 2;
                ldsm_x4(sb + OFF_WH + eoff, w_h + np * 4);
                ldsm_x4(sb + OFF_WL + eoff, w_l + np * 4);
            }
#pragma unroll
            for (int mt = 0; mt < 2; mt++)
#pragma unroll
                for (int nt = 0; nt < 4; nt++) {
                    const int bi = (nt >> 1) * 4 + (nt & 1) * 2;
                    mma_bf16(acc[mt][nt], a_h + mt * 4, w_h + bi);
                    mma_bf16(acc[mt][nt], a_h + mt * 4, w_l + bi);
                    mma_bf16(acc[mt][nt], a_l + mt * 4, w_h + bi);
                }
        }
    }

    // ---- stage-1 epilogue: write xtA AND stash split-bf16 tile in smem ----
    __syncthreads();
    const int tr = lane >> 2;
    const int tc = (lane & 3) * 2;
    {
        float2 bb[4];
#pragma unroll
        for (int nt = 0; nt < 4; nt++)
            bb[nt] = *(const float2*)&bias[wn + nt * 8 + tc];
        char* dh = sm + OFF_AH;
        char* dl = sm + OFF_AL;
#pragma unroll
        for (int mt = 0; mt < 2; mt++) {
#pragma unroll
            for (int half = 0; half < 2; half++) {
                const int rl = wm + mt * 16 + tr + half * 8;
                const int r = row0 + rl;
                const int n = nid[r];
                const float* erow = &emb[(size_t)n * CH];
                float* orow = &outA[(size_t)r * CH];
#pragma unroll
                for (int nt = 0; nt < 4; nt++) {
                    const int col = wn + nt * 8 + tc;
                    float2 e = *(const float2*)&erow[col];
                    float2 o;
                    o.x = acc[mt][nt][half * 2 + 0] + bb[nt].x + e.x;
                    o.y = acc[mt][nt][half * 2 + 1] + bb[nt].y + e.y;
                    *(float2*)&orow[col] = o;
                    uint32_t h, l;
                    split2(o.x, o.y, h, l);
                    uint32_t off = (uint32_t)(rl * AWS + col) * 2;
                    *(uint32_t*)(dh + off) = h;
                    *(uint32_t*)(dl + off) = l;
                }
            }
        }
    }
    // ---- load W0 split tile ----
    {
        const uint32_t* sh = W0h + wr * 32 + seg * 8;
        const uint32_t* sl = W0l + wr * 32 + seg * 8;
        uint32_t* dh = (uint32_t*)(sm + OFF_WH) + wr * 36 + seg * 8;
        uint32_t* dl = (uint32_t*)(sm + OFF_WL) + wr * 36 + seg * 8;
        uint4 a0 = *(const uint4*)sh;
        uint4 a1 = *(const uint4*)(sh + 4);
        uint4 b0 = *(const uint4*)sl;
        uint4 b1 = *(const uint4*)(sl + 4);
        *(uint4*)dh = a0;
        *(uint4*)(dh + 4) = a1;
        *(uint4*)dl = b0;
        *(uint4*)(dl + 4) = b1;
    }
    __syncthreads();

    // ---- stage 2: K=64 mma with W0 ----
#pragma unroll
    for (int mt = 0; mt < 2; mt++)
#pragma unroll
        for (int nt = 0; nt < 4; nt++)
#pragma unroll
            for (int j = 0; j < 4; j++) acc[mt][nt][j] = 0.f;

#pragma unroll
    for (int ks = 0; ks < 4; ks++) {
        const int kcol = ks * 16;
        uint32_t a_h[8], a_l[8], w_h[8], w_l[8];
#pragma unroll
        for (int mt = 0; mt < 2; mt++) {
            uint32_t eoff = (uint32_t)((a_row + mt * 16) * AWS + kcol + a_koff) * 2;
            ldsm_x4(sb + OFF_AH + eoff, a_h + mt * 4);
            ldsm_x4(sb + OFF_AL + eoff, a_l + mt * 4);
        }
#pragma unroll
        for (int np = 0; np < 2; np++) {
            uint32_t eoff = (uint32_t)((b_row + np * 16) * AWS + kcol + b_koff) * 2;
            ldsm_x4(sb + OFF_WH + eoff, w_h + np * 4);
            ldsm_x4(sb + OFF_WL + eoff, w_l + np * 4);
        }
#pragma unroll
        for (int mt = 0; mt < 2; mt++)
#pragma unroll
            for (int nt = 0; nt < 4; nt++) {
                const int bi = (nt >> 1) * 4 + (nt & 1) * 2;
                mma_bf16(acc[mt][nt], a_h + mt * 4, w_h + bi);
                mma_bf16(acc[mt][nt], a_h + mt * 4, w_l + bi);
                mma_bf16(acc[mt][nt], a_l + mt * 4, w_h + bi);
            }
    }

    {
        float2 bb[4];
#pragma unroll
        for (int nt = 0; nt < 4; nt++)
            bb[nt] = *(const float2*)&bias0[wn + nt * 8 + tc];
#pragma unroll
        for (int mt = 0; mt < 2; mt++) {
#pragma unroll
            for (int half = 0; half < 2; half++) {
                const int r = row0 + wm + mt * 16 + tr + half * 8;
                float* orow = &outB[(size_t)r * CH];
#pragma unroll
                for (int nt = 0; nt < 4; nt++) {
                    const int col = wn + nt * 8 + tc;
                    float2 o;
                    o.x = acc[mt][nt][half * 2 + 0] + bb[nt].x;
                    o.y = acc[mt][nt][half * 2 + 1] + bb[nt].y;
                    *(float2*)&orow[col] = o;
                }
            }
        }
    }
}

// =================== thesis base (layer 1): out = relu(x)@Wr^T + b ===================
__global__ __launch_bounds__(256, 2) void thesis_base_kernel(
    const float* __restrict__ Xin,
    const uint32_t* __restrict__ Wh, const uint32_t* __restrict__ Wl,
    const float* __restrict__ bias, float* __restrict__ out, int relu_in) {
    extern __shared__ char sm[];
    const uint32_t sb = smem_u32(sm);
    const int tid = threadIdx.x;
    const int wid = tid >> 5;
    const int lane = tid & 31;
    const int wm = (wid & 3) * 32;
    const int wn = (wid >> 2) * 32;
    const int row0 = blockIdx.x * 128;

    const int arow = wid * 16 + (lane >> 4);
    const int acol = (lane & 15) * 4;
    const int wr = tid >> 2, seg = tid & 3;

    {
        char* dh = sm + OFF_AH;
        char* dl = sm + OFF_AL;
#pragma unroll
        for (int j = 0; j < 8; j++) {
            const int r = arow + j * 2;
            float4 v = *(const float4*)&Xin[(size_t)(row0 + r) * CH + acol];
            if (relu_in) {
                v.x = fmaxf(v.x, 0.f); v.y = fmaxf(v.y, 0.f);
                v.z = fmaxf(v.z, 0.f); v.w = fmaxf(v.w, 0.f);
            }
            uint32_t h0, l0, h1, l1;
            split2(v.x, v.y, h0, l0);
            split2(v.z, v.w, h1, l1);
            uint32_t off = (uint32_t)(r * AWS + acol) * 2;
            *(uint2*)(dh + off) = make_uint2(h0, h1);
            *(uint2*)(dl + off) = make_uint2(l0, l1);
        }
    }
    {
        const uint32_t* sh = Wh + wr * 32 + seg * 8;
        const uint32_t* sl = Wl + wr * 32 + seg * 8;
        uint32_t* dh = (uint32_t*)(sm + OFF_WH) + wr * 36 + seg * 8;
        uint32_t* dl = (uint32_t*)(sm + OFF_WL) + wr * 36 + seg * 8;
        uint4 a0 = *(const uint4*)sh;
        uint4 a1 = *(const uint4*)(sh + 4);
        uint4 b0 = *(const uint4*)sl;
        uint4 b1 = *(const uint4*)(sl + 4);
        *(uint4*)dh = a0;
        *(uint4*)(dh + 4) = a1;
        *(uint4*)dl = b0;
        *(uint4*)(dl + 4) = b1;
    }
    __syncthreads();

    float acc[2][4][4];
#pragma unroll
    for (int mt = 0; mt < 2; mt++)
#pragma unroll
        for (int nt = 0; nt < 4; nt++)
#pragma unroll
            for (int j = 0; j < 4; j++) acc[mt][nt][j] = 0.f;

    const int a_row = wm + (lane & 15);
    const int a_koff = (lane >> 4) * 8;
    const int g = lane >> 3;
    const int b_row = wn + ((g >> 1) << 3) + (lane & 7);
    const int b_koff = (g & 1) << 3;

#pragma unroll
    for (int ks = 0; ks < 4; ks++) {
        const int kcol = ks * 16;
        uint32_t a_h[8], a_l[8], w_h[8], w_l[8];
#pragma unroll
        for (int mt = 0; mt < 2; mt++) {
            uint32_t eoff = (uint32_t)((a_row + mt * 16) * AWS + kcol + a_koff) * 2;
            ldsm_x4(sb + OFF_AH + eoff, a_h + mt * 4);
            ldsm_x4(sb + OFF_AL + eoff, a_l + mt * 4);
        }
#pragma unroll
        for (int np = 0; np < 2; np++) {
            uint32_t eoff = (uint32_t)((b_row + np * 16) * AWS + kcol + b_koff) * 2;
            ldsm_x4(sb + OFF_WH + eoff, w_h + np * 4);
            ldsm_x4(sb + OFF_WL + eoff, w_l + np * 4);
        }
#pragma unroll
        for (int mt = 0; mt < 2; mt++)
#pragma unroll
            for (int nt = 0; nt < 4; nt++) {
                const int bi = (nt >> 1) * 4 + (nt & 1) * 2;
                mma_bf16(acc[mt][nt], a_h + mt * 4, w_h + bi);
                mma_bf16(acc[mt][nt], a_h + mt * 4, w_l + bi);
                mma_bf16(acc[mt][nt], a_l + mt * 4, w_h + bi);
            }
    }

    const int tr = lane >> 2;
    const int tc = (lane & 3) * 2;
    float2 bb[4];
#pragma unroll
    for (int nt = 0; nt < 4; nt++)
        bb[nt] = *(const float2*)&bias[wn + nt * 8 + tc];
#pragma unroll
    for (int mt = 0; mt < 2; mt++) {
#pragma unroll
        for (int half = 0; half < 2; half++) {
            const int r = row0 + wm + mt * 16 + tr + half * 8;
            float* orow = &out[(size_t)r * CH];
#pragma unroll
            for (int nt = 0; nt < 4; nt++) {
                const int col = wn + nt * 8 + tc;
                float2 o;
                o.x = acc[mt][nt][half * 2 + 0] + bb[nt].x;
                o.y = acc[mt][nt][half * 2 + 1] + bb[nt].y;
                *(float2*)&orow[col] = o;
            }
        }
    }
}

// ---------------- small kernels ----------------
__global__ __launch_bounds__(256) void zero_deg_kernel(int* degt, int* degm) {
    int i = blockIdx.x * 256 + threadIdx.x;
    if (i < NT) degt[i] = 0;
    if (i < NM) degm[i] = 0;
}

__global__ __launch_bounds__(256) void degree_kernel(const int* __restrict__ esrc,
                                                     const int* __restrict__ edst,
                                                     int* degt, int* degm) {
    int e = blockIdx.x * 256 + threadIdx.x;
    if (e < NE) {
        atomicAdd(&degm[edst[e]], 1);
        atomicAdd(&degt[esrc[e]], 1);
    }
}

__global__ __launch_bounds__(256) void invdeg_kernel(const int* __restrict__ degt,
                                                     float* __restrict__ invt) {
    int i = blockIdx.x * 256 + threadIdx.x;
    if (i < NT) {
        int d = degt[i];
        invt[i] = 1.0f / (float)(d > 0 ? d : 1);
    }
}

__global__ __launch_bounds__(256) void copy_xm_kernel(const float* __restrict__ embm,
                                                      const int* __restrict__ mid,
                                                      float* __restrict__ xm) {
    int idx = blockIdx.x * 256 + threadIdx.x;
    int i = idx >> 4;
    int q = (idx & 15) << 2;
    int n = mid[i];
    *(float4*)&xm[(size_t)i * CH + q] = *(const float4*)&embm[(size_t)n * CH + q];
}

// ---------------- z_m = x_m @ Wl_mt^T  (+ zero aggm slice) ----------------
__global__ __launch_bounds__(256) void zm_kernel(const float* __restrict__ Xin,
                                                 const float* __restrict__ W,
                                                 float* __restrict__ out,
                                                 float* __restrict__ aggm) {
    __shared__ float Xs[64 * 68];
    __shared__ float Ws[64 * 68];
    int tid = threadIdx.x;
    int tx = tid & 15, ty = tid >> 4;
    int row0 = blockIdx.x * 64;
    {
        float4* dst = (float4*)&aggm[(size_t)row0 * CH];
        float4 z = make_float4(0.f, 0.f, 0.f, 0.f);
#pragma unroll
        for (int i = 0; i < 4; i++) dst[i * 256 + tid] = z;
    }
#pragma unroll
    for (int it = 0; it < 4; it++) {
        int f = it * 256 + tid;
        int r = f >> 4;
        int kq = (f & 15) << 2;
        *(float4*)&Xs[r * 68 + kq] = *(const float4*)&Xin[(size_t)(row0 + r) * CH + kq];
        float4 v = *(const float4*)&W[r * CH + kq];
        Ws[(kq + 0) * 68 + r] = v.x;
        Ws[(kq + 1) * 68 + r] = v.y;
        Ws[(kq + 2) * 68 + r] = v.z;
        Ws[(kq + 3) * 68 + r] = v.w;
    }
    __syncthreads();
    float acc[4][4] = {};
#pragma unroll 8
    for (int k = 0; k < 64; k++) {
        float4 b4 = *(const float4*)&Ws[k * 68 + tx * 4];
#pragma unroll
        for (int i = 0; i < 4; i++) {
            float a = Xs[(ty * 4 + i) * 68 + k];
            acc[i][0] += a * b4.x;
            acc[i][1] += a * b4.y;
            acc[i][2] += a * b4.z;
            acc[i][3] += a * b4.w;
        }
    }
#pragma unroll
    for (int i = 0; i < 4; i++) {
        int r = row0 + ty * 4 + i;
        float4 o = make_float4(acc[i][0], acc[i][1], acc[i][2], acc[i][3]);
        *(float4*)&out[(size_t)r * CH + tx * 4] = o;
    }
}

// ---------------- fused edge scatter ----------------
__global__ __launch_bounds__(256) void scatter_fused_kernel(
    const float* __restrict__ xt, const float* __restrict__ zm,
    const float* __restrict__ invt,
    const int* __restrict__ esrc, const int* __restrict__ edst,
    float* aggm, float* xtout, int relu_in) {
    int idx = blockIdx.x * 256 + threadIdx.x;
    int e = idx >> 4;
    int q = (idx & 15) << 2;
    int s = __ldg(&esrc[e]);
    int d = __ldg(&edst[e]);
    float inv = __ldg(&invt[s]);
    float4 v = *(const float4*)&xt[(size_t)s * CH + q];
    if (relu_in) {
        v.x = fmaxf(v.x, 0.f); v.y = fmaxf(v.y, 0.f);
        v.z = fmaxf(v.z, 0.f); v.w = fmaxf(v.w, 0.f);
    }
    float4 w = *(const float4*)&zm[(size_t)d * CH + q];
    w.x *= inv; w.y *= inv; w.z *= inv; w.w *= inv;
    float* pm = &aggm[(size_t)d * CH + q];
    float* pt = &xtout[(size_t)s * CH + q];
    asm volatile("red.global.add.v4.f32 [%0], {%1,%2,%3,%4};"
                 :: "l"(pm), "f"(v.x), "f"(v.y), "f"(v.z), "f"(v.w) : "memory");
    asm volatile("red.global.add.v4.f32 [%0], {%1,%2,%3,%4};"
                 :: "l"(pt), "f"(w.x), "f"(w.y), "f"(w.z), "f"(w.w) : "memory");
}

// ---------------- mentor update ----------------
__global__ __launch_bounds__(256) void mentor_kernel(const float* __restrict__ xm,
                                                     const float* __restrict__ aggm,
                                                     const int* __restrict__ degm,
                                                     const float* __restrict__ Wl,
                                                     const float* __restrict__ Wr,
                                                     const float* __restrict__ bias,
                                                     float* __restrict__ out, int relu) {
    __shared__ float Xs[64 * 68];
    __shared__ float Ws[64 * 68];
    int tid = threadIdx.x;
    int tx = tid & 15, ty = tid >> 4;
    int row0 = blockIdx.x * 64;
    float acc[4][4] = {};

    for (int p = 0; p < 2; p++) {
        __syncthreads();
        const float* A = p ? xm : aggm;
        const float* W = p ? Wr : Wl;
#pragma unroll
        for (int it = 0; it < 4; it++) {
            int f = it * 256 + tid;
            int r = f >> 4;
            int kq = (f & 15) << 2;
            float4 v = *(const float4*)&A[(size_t)(row0 + r) * CH + kq];
            if (p == 0) {
                int dg = degm[row0 + r];
                float inv = 1.0f / (float)(dg > 0 ? dg : 1);
                v.x *= inv; v.y *= inv; v.z *= inv; v.w *= inv;
            }
            *(float4*)&Xs[r * 68 + kq] = v;
            float4 wv = *(const float4*)&W[r * CH + kq];
            Ws[(kq + 0) * 68 + r] = wv.x;
            Ws[(kq + 1) * 68 + r] = wv.y;
            Ws[(kq + 2) * 68 + r] = wv.z;
            Ws[(kq + 3) * 68 + r] = wv.w;
        }
        __syncthreads();
#pragma unroll 8
        for (int k = 0; k < 64; k++) {
            float4 b4 = *(const float4*)&Ws[k * 68 + tx * 4];
#pragma unroll
            for (int i = 0; i < 4; i++) {
                float a = Xs[(ty * 4 + i) * 68 + k];
                acc[i][0] += a * b4.x;
                acc[i][1] += a * b4.y;
                acc[i][2] += a * b4.z;
                acc[i][3] += a * b4.w;
            }
        }
    }
    float4 bb = *(const float4*)&bias[tx * 4];
#pragma unroll
    for (int i = 0; i < 4; i++) {
        int r = row0 + ty * 4 + i;
        float4 o;
        o.x = acc[i][0] + bb.x;
        o.y = acc[i][1] + bb.y;
        o.z = acc[i][2] + bb.z;
        o.w = acc[i][3] + bb.w;
        if (relu) {
            o.x = fmaxf(o.x, 0.f); o.y = fmaxf(o.y, 0.f);
            o.z = fmaxf(o.z, 0.f); o.w = fmaxf(o.w, 0.f);
        }
        *(float4*)&out[(size_t)r * CH + tx * 4] = o;
    }
}

// ---------------- edge dot classifier ----------------
__global__ __launch_bounds__(256) void dot_kernel(const float* __restrict__ xt,
                                                  const float* __restrict__ xm,
                                                  const int* __restrict__ els,
                                                  const int* __restrict__ eld,
                                                  float* __restrict__ out) {
    int idx = blockIdx.x * 256 + threadIdx.x;
    int e = idx >> 4;
    int q = (idx & 15) << 2;
    int s = __ldg(&els[e]);
    int d = __ldg(&eld[e]);
    float4 a = *(const float4*)&xt[(size_t)s * CH + q];
    float4 b = *(const float4*)&xm[(size_t)d * CH + q];
    float p = a.x * b.x + a.y * b.y + a.z * b.z + a.w * b.w;
    p += __shfl_xor_sync(0xffffffffu, p, 8);
    p += __shfl_xor_sync(0xffffffffu, p, 4);
    p += __shfl_xor_sync(0xffffffffu, p, 2);
    p += __shfl_xor_sync(0xffffffffu, p, 1);
    if ((idx & 15) == 0) out[e] = p;
}

// ---------------- launcher ----------------
extern "C" void kernel_launch(void* const* d_in, const int* in_sizes, int n_in,
                              void* d_out, int out_size) {
    const float* x_thesis = (const float*)d_in[0];
    const int*   tnid     = (const int*)d_in[1];
    const int*   mnid     = (const int*)d_in[2];
    const int*   esrc     = (const int*)d_in[3];
    const int*   edst     = (const int*)d_in[4];
    const int*   els      = (const int*)d_in[5];
    const int*   eld      = (const int*)d_in[6];
    const float* linW     = (const float*)d_in[7];
    const float* linb     = (const float*)d_in[8];
    const float* embt     = (const float*)d_in[9];
    const float* embm     = (const float*)d_in[10];
    float* out = (float*)d_out;

    float *p_xtA, *p_xtB, *p_xmA, *p_xmB, *p_aggm, *p_zm, *p_invt;
    int *p_degt, *p_degm;
    uint32_t *p_eWh, *p_eWl, *p_W0h, *p_W0l, *p_W1h, *p_W1l;
    cudaGetSymbolAddress((void**)&p_xtA, g_xtA);
    cudaGetSymbolAddress((void**)&p_xtB, g_xtB);
    cudaGetSymbolAddress((void**)&p_xmA, g_xmA);
    cudaGetSymbolAddress((void**)&p_xmB, g_xmB);
    cudaGetSymbolAddress((void**)&p_aggm, g_aggm);
    cudaGetSymbolAddress((void**)&p_zm, g_zm);
    cudaGetSymbolAddress((void**)&p_degt, g_degt);
    cudaGetSymbolAddress((void**)&p_degm, g_degm);
    cudaGetSymbolAddress((void**)&p_invt, g_invdegt);
    cudaGetSymbolAddress((void**)&p_eWh, g_encWh);
    cudaGetSymbolAddress((void**)&p_eWl, g_encWl);
    cudaGetSymbolAddress((void**)&p_W0h, g_Wt0h);
    cudaGetSymbolAddress((void**)&p_W0l, g_Wt0l);
    cudaGetSymbolAddress((void**)&p_W1h, g_Wt1h);
    cudaGetSymbolAddress((void**)&p_W1l, g_Wt1l);

    cudaFuncSetAttribute(encoder_fused_kernel,
                         cudaFuncAttributeMaxDynamicSharedMemorySize, ENC_SMEM);
    cudaFuncSetAttribute(thesis_base_kernel,
                         cudaFuncAttributeMaxDynamicSharedMemorySize, TB_SMEM);

    // weight pre-splits
    split_w_kernel<<<(CH * FT / 2 + 255) / 256, 256>>>(linW, p_eWh, p_eWl, CH * FT / 2);
    split_w_kernel<<<(CH * CH / 2 + 255) / 256, 256>>>((const float*)d_in[15], p_W0h, p_W0l, CH * CH / 2);
    split_w_kernel<<<(CH * CH / 2 + 255) / 256, 256>>>((const float*)d_in[21], p_W1h, p_W1l, CH * CH / 2);
    // fused encoder + layer-0 thesis base
    encoder_fused_kernel<<<NT / 128, 256, ENC_SMEM>>>(x_thesis, p_eWh, p_eWl, linb, tnid, embt,
                                                      p_W0h, p_W0l, (const float*)d_in[16],
                                                      p_xtA, p_xtB);
    // graph prep
    zero_deg_kernel<<<(NT + 255) / 256, 256>>>(p_degt, p_degm);
    degree_kernel<<<(NE + 255) / 256, 256>>>(esrc, edst, p_degt, p_degm);
    invdeg_kernel<<<(NT + 255) / 256, 256>>>(p_degt, p_invt);
    copy_xm_kernel<<<NM * 16 / 256, 256>>>(embm, mnid, p_xmA);

    // ---- layer 0 ----
    zm_kernel<<<NM / 64, 256>>>(p_xmA, (const float*)d_in[14], p_zm, p_aggm);
    scatter_fused_kernel<<<NE * 16 / 256, 256>>>(p_xtA, p_zm, p_invt, esrc, edst,
                                                 p_aggm, p_xtB, 0);
    mentor_kernel<<<NM / 64, 256>>>(p_xmA, p_aggm, p_degm,
                                    (const float*)d_in[11], (const float*)d_in[12],
                                    (const float*)d_in[13], p_xmB, 1);

    // ---- layer 1 ----
    zm_kernel<<<NM / 64, 256>>>(p_xmB, (const float*)d_in[20], p_zm, p_aggm);
    thesis_base_kernel<<<NT / 128, 256, TB_SMEM>>>(p_xtB, p_W1h, p_W1l,
                                                   (const float*)d_in[22], p_xtA, 1);
    scatter_fused_kernel<<<NE * 16 / 256, 256>>>(p_xtB, p_zm, p_invt, esrc, edst,
                                                 p_aggm, p_xtA, 1);
    mentor_kernel<<<NM / 64, 256>>>(p_xmB, p_aggm, p_degm,
                                    (const float*)d_in[17], (const float*)d_in[18],
                                    (const float*)d_in[19], p_xmA, 0);

    dot_kernel<<<NEL * 16 / 256, 256>>>(p_xtA, p_xmA, els, eld, out);
}